// round 12
// baseline (speedup 1.0000x reference)
#include <cuda_runtime.h>
#include <cuda_fp16.h>
#include <math.h>
#include <stdint.h>

#define B_   32
#define N_   512
#define D_   768
#define NBR_ 4
#define L_   2
#define FH_  256
#define NC_  2
#define RB_  (NBR_*B_)   // 128

#define ISD 0.0360843918243516f  // 1/sqrt(768)

typedef __half h16;

// ---------------- scratch (device globals; allocation-free) ----------------
__device__ __align__(256) h16 g_Wq16[NBR_*L_*D_*D_];
__device__ __align__(256) h16 g_Wk16[NBR_*L_*D_*D_];
__device__ __align__(256) h16 g_Mt16[NBR_*L_*D_*D_];   // (Wq@Wk^T)^T = Wk@Wq^T [n][k]
__device__ __align__(256) h16 g_fe16[B_*N_*D_];        // feature fp16
__device__ __align__(256) h16 g_fT16[B_*D_*N_];        // feature^T fp16
__device__ __align__(256) h16 g_t16[NBR_*B_*N_*D_];    // feat@Mw
__device__ __align__(256) h16 g_gT16[RB_*N_*N_];       // layer-1 gate^T fp16 [z][j][i]
__device__ __align__(256) h16 g_gp16[RB_*N_*N_];       // dis*gateT*dis
__device__ __align__(256) h16 g_f116[RB_*N_*D_];       // feat1
__device__ float g_degp [RB_*N_*16];       // layer-1 degree partials
__device__ float g_disv [RB_*N_];          // layer-1 D^-1/2
__device__ float g_degp2[RB_*N_*16];       // layer-2 degree partials
__device__ float g_dis2 [RB_*N_];          // layer-2 D^-1/2
__device__ float g_gcol2[RB_*N_];          // layer-2 gate column j=511
__device__ float g_node2[RB_*D_];          // layer-2 node-511 features

// ===================== warp-MMA (fp16 HMMA) machinery =======================
// 128x128 C-tile, K-chunk 64, 256 threads = 8 warps in 2(m) x 4(n).
// Single-pass fp16. 3-stage cp.async, ONE __syncthreads per chunk, 2 CTAs/SM.

#define KPAD     72                       // fp16 per smem row (144 B)
#define TILE_B   (128*KPAD*2)             // 18432 B per operand tile
#define OFF_A    0
#define OFF_B    (TILE_B)
#define STAGE_B  (2*TILE_B)               // 36864
#define NSTAGE   3
#define SMEM_REQ (NSTAGE*STAGE_B)         // 110592 -> 2 CTAs/SM

__device__ __forceinline__ uint32_t smem_u32(const void* p) {
    uint32_t a;
    asm("{ .reg .u64 t; cvta.to.shared.u64 t, %1; cvt.u32.u64 %0, t; }"
        : "=r"(a) : "l"(p));
    return a;
}

__device__ __forceinline__ void ldsm4(uint32_t r[4], uint32_t addr) {
    asm volatile("ldmatrix.sync.aligned.m8n8.x4.shared.b16 {%0,%1,%2,%3}, [%4];"
                 : "=r"(r[0]), "=r"(r[1]), "=r"(r[2]), "=r"(r[3]) : "r"(addr));
}

__device__ __forceinline__ void mma_fp16(float c[4], const uint32_t a[4],
                                         uint32_t b0, uint32_t b1) {
    asm volatile(
        "mma.sync.aligned.m16n8k16.row.col.f32.f16.f16.f32 "
        "{%0,%1,%2,%3}, {%4,%5,%6,%7}, {%8,%9}, {%0,%1,%2,%3};"
        : "+f"(c[0]), "+f"(c[1]), "+f"(c[2]), "+f"(c[3])
        : "r"(a[0]), "r"(a[1]), "r"(a[2]), "r"(a[3]), "r"(b0), "r"(b1));
}

__device__ __forceinline__ void cpa16(uint32_t dst, const void* src) {
    asm volatile("cp.async.cg.shared.global [%0], [%1], 16;"
                 :: "r"(dst), "l"(src) : "memory");
}

// issue cp.async for one 64-K chunk: 2 tiles of 128x64 fp16 (128 B/row)
__device__ __forceinline__ void cpa_chunk(uint32_t sdst,
                                          const h16* __restrict__ A, int lda,
                                          const h16* __restrict__ Bm, int ldb,
                                          int k0) {
    const int tid = threadIdx.x;
    #pragma unroll
    for (int it = 0; it < 8; it++) {
        const int idx  = it * 256 + tid;   // 2048 = 2 tiles * 128 rows * 8 groups
        const int tile = idx >> 10;
        const int row  = (idx >> 3) & 127;
        const int grp  = idx & 7;
        const h16* src = tile ? Bm : A;
        const int ld   = tile ? ldb : lda;
        cpa16(sdst + (tile ? OFF_B : OFF_A) + row * 144 + grp * 16,
              src + (size_t)row * ld + k0 + grp * 8);
    }
}

// one 64-K chunk of MMAs; acc[16][4] per thread
__device__ __forceinline__ void mma_chunk(uint32_t sbase, float (*acc)[4]) {
    const int lane = threadIdx.x & 31;
    const int wid  = threadIdx.x >> 5;
    const int wr = wid >> 2, wc = wid & 3;
    uint32_t aoff[4], boff[2];
    #pragma unroll
    for (int mt = 0; mt < 4; mt++)
        aoff[mt] = (uint32_t)(((wr*64 + mt*16 + (lane & 7) + ((lane >> 3) & 1) * 8) * KPAD
                               + (lane >> 4) * 8) * 2);
    #pragma unroll
    for (int pr = 0; pr < 2; pr++)
        boff[pr] = (uint32_t)(((wc*32 + pr*16 + ((lane >> 4) & 1) * 8 + (lane & 7)) * KPAD
                               + ((lane >> 3) & 1) * 8) * 2);
    #pragma unroll
    for (int ks = 0; ks < 4; ks++) {
        const uint32_t kb = ks * 32;       // 16 fp16 = 32 B
        uint32_t A[4][4], Bv[4][2];
        #pragma unroll
        for (int mt = 0; mt < 4; mt++) ldsm4(A[mt], sbase + OFF_A + aoff[mt] + kb);
        #pragma unroll
        for (int pr = 0; pr < 2; pr++) {
            uint32_t rr[4];
            ldsm4(rr, sbase + OFF_B + boff[pr] + kb);
            Bv[pr*2][0] = rr[0]; Bv[pr*2][1] = rr[1];
            Bv[pr*2+1][0] = rr[2]; Bv[pr*2+1][1] = rr[3];
        }
        #pragma unroll
        for (int mt = 0; mt < 4; mt++)
            #pragma unroll
            for (int nt = 0; nt < 4; nt++)
                mma_fp16(acc[mt*4+nt], A[mt], Bv[nt][0], Bv[nt][1]);
    }
}

// full mainloop: 3-stage cp.async, one __syncthreads per chunk
__device__ __forceinline__ void mma_main(const h16* __restrict__ A, int lda,
                                         const h16* __restrict__ Bm, int ldb,
                                         int kchunks, char* smb, float (*acc)[4]) {
    uint32_t sb = smem_u32(smb);
    cpa_chunk(sb, A, lda, Bm, ldb, 0);
    asm volatile("cp.async.commit_group;" ::: "memory");
    cpa_chunk(sb + STAGE_B, A, lda, Bm, ldb, 64);
    asm volatile("cp.async.commit_group;" ::: "memory");
    int buf = 0, pf = 2;
    for (int c = 0; c < kchunks; c++) {
        if (c + 1 < kchunks) {
            asm volatile("cp.async.wait_group 1;" ::: "memory");
        } else {
            asm volatile("cp.async.wait_group 0;" ::: "memory");
        }
        __syncthreads();   // chunk c visible to all; all warps done with buf (c-1)%3
        if (c + 2 < kchunks) {
            cpa_chunk(sb + pf * STAGE_B, A, lda, Bm, ldb, (c + 2) * 64);
            asm volatile("cp.async.commit_group;" ::: "memory");
        }
        mma_chunk(sb + buf * STAGE_B, acc);
        buf = (buf == NSTAGE - 1) ? 0 : buf + 1;
        pf  = (pf  == NSTAGE - 1) ? 0 : pf  + 1;
    }
    __syncthreads();       // protect smem reuse by epilogues
}

// store acc as fp16
__device__ __forceinline__ void store_h(float (*acc)[4], h16* __restrict__ C, int ldc) {
    const int lane = threadIdx.x & 31;
    const int wid  = threadIdx.x >> 5;
    const int wr = wid >> 2, wc = wid & 3;
    #pragma unroll
    for (int mt = 0; mt < 4; mt++) {
        const int r0 = wr*64 + mt*16 + (lane >> 2);
        #pragma unroll
        for (int nt = 0; nt < 4; nt++) {
            const int cn = wc*32 + nt*8 + (lane & 3) * 2;
            float* f = acc[mt*4+nt];
            *(__half2*)(C + (size_t)r0 * ldc + cn)     = __floats2half2_rn(f[0], f[1]);
            *(__half2*)(C + (size_t)(r0+8) * ldc + cn) = __floats2half2_rn(f[2], f[3]);
        }
    }
}

// ============================ kernels =======================================

// elementwise fp32 -> fp16
__global__ void __launch_bounds__(256) k_h(const float* __restrict__ src,
                                           h16* __restrict__ dst, int n4) {
    const int i = blockIdx.x * 256 + threadIdx.x;
    if (i >= n4) return;
    float4 v = ((const float4*)src)[i];
    ((__half2*)dst)[i*2]   = __floats2half2_rn(v.x, v.y);
    ((__half2*)dst)[i*2+1] = __floats2half2_rn(v.z, v.w);
}

// featT[b][d][i] = feature[b][i][d], fp16
__global__ void __launch_bounds__(256) k_tr(const float* __restrict__ f) {
    __shared__ float t[32][33];
    const int b = blockIdx.z;
    const int i0 = blockIdx.x * 32, d0 = blockIdx.y * 32;
    const int tx = threadIdx.x & 31, ty = threadIdx.x >> 5;
    #pragma unroll
    for (int s = 0; s < 32; s += 8)
        t[ty + s][tx] = f[((size_t)b * N_ + i0 + ty + s) * D_ + d0 + tx];
    __syncthreads();
    #pragma unroll
    for (int s = 0; s < 32; s += 8)
        g_fT16[((size_t)b * D_ + d0 + ty + s) * N_ + i0 + tx] = __float2half(t[tx][ty + s]);
}

// Mt[z] = Wk[z] @ Wq[z]^T
__global__ void __launch_bounds__(256, 2)
k_mw_tc() {
    extern __shared__ char smb[];
    const int z = blockIdx.z, m0 = blockIdx.x * 128, n0 = blockIdx.y * 128;
    const size_t zo = (size_t)z * D_ * D_;
    float acc[16][4] = {};
    mma_main(g_Wk16 + zo + (size_t)m0 * D_, D_,
             g_Wq16 + zo + (size_t)n0 * D_, D_, 12, smb, acc);
    store_h(acc, g_Mt16 + zo + (size_t)m0 * D_ + n0, D_);
}

// t = featIn @ Mw[r,layer]
__global__ void __launch_bounds__(256, 2)
k_tf_tc(int layer) {
    extern __shared__ char smb[];
    const int r = blockIdx.z, m0 = blockIdx.x * 128, n0 = blockIdx.y * 128;
    const size_t ao = (size_t)r * B_ * N_ * D_ + (size_t)m0 * D_;
    const h16* Ap = layer ? (g_f116 + ao) : (g_fe16 + (size_t)m0 * D_);
    const size_t bo = (size_t)(r * L_ + layer) * D_ * D_ + (size_t)n0 * D_;
    float acc[16][4] = {};
    mma_main(Ap, D_, g_Mt16 + bo, D_, 12, smb, acc);
    store_h(acc, g_t16 + ((size_t)r * B_ * N_ + m0) * D_ + n0, D_);
}

// logits = t @ featB^T; gate epilogue + deterministic row-sum partials.
__global__ void __launch_bounds__(256, 2)
k_gate_tc(const float* __restrict__ pmask, int layer) {
    extern __shared__ char smb[];
    const int z = blockIdx.z, b = z & (B_ - 1);
    const int i0 = blockIdx.x * 128, j0 = blockIdx.y * 128, jt = blockIdx.y;
    const size_t ao = (size_t)z * N_ * D_ + (size_t)i0 * D_;
    const size_t bo = layer ? ((size_t)z * N_ * D_ + (size_t)j0 * D_)
                            : ((size_t)b * N_ * D_ + (size_t)j0 * D_);
    const h16* Bp = layer ? (g_f116 + bo) : (g_fe16 + bo);
    float acc[16][4] = {};
    mma_main(g_t16 + ao, D_, Bp, D_, 12, smb, acc);

    const int lane = threadIdx.x & 31;
    const int wid  = threadIdx.x >> 5;
    const int wr = wid >> 2, wc = wid & 3;
    h16* sT = (h16*)smb;                   // [128][136] j-major fp16 transpose buffer

    float* degp = layer ? g_degp2 : g_degp;
    #pragma unroll
    for (int mt = 0; mt < 4; mt++) {
        const int r0 = wr*64 + mt*16 + (lane >> 2);
        const float pmi0 = pmask[b*N_ + i0 + r0];
        const float pmi1 = pmask[b*N_ + i0 + r0 + 8];
        float rs0 = 0.f, rs1 = 0.f;
        #pragma unroll
        for (int nt = 0; nt < 4; nt++) {
            const int cn = wc*32 + nt*8 + (lane & 3) * 2;
            const float pj0 = pmask[b*N_ + j0 + cn];
            const float pj1 = pmask[b*N_ + j0 + cn + 1];
            float* f = acc[mt*4+nt];
            #pragma unroll
            for (int e = 0; e < 4; e++) {
                const float pmi = (e < 2) ? pmi0 : pmi1;
                const float pmj = (e & 1) ? pj1 : pj0;
                const float s = f[e] * ISD;
                const float p = 1.f / (1.f + __expf(-s));
                const float g = fminf(fmaxf(fmaf(p, 1.2f, -0.1f), 0.f), 1.f) * pmi * pmj;
                const int jl = cn + (e & 1);
                const int il = (e < 2) ? r0 : (r0 + 8);
                if (layer == 0) {
                    sT[jl * 136 + il] = __float2half(g);
                } else if (j0 + jl == N_ - 1) {
                    g_gcol2[z*N_ + i0 + il] = g;
                }
                if (e < 2) rs0 += g; else rs1 += g;
            }
        }
        rs0 += __shfl_xor_sync(0xffffffffu, rs0, 1);
        rs0 += __shfl_xor_sync(0xffffffffu, rs0, 2);
        rs1 += __shfl_xor_sync(0xffffffffu, rs1, 1);
        rs1 += __shfl_xor_sync(0xffffffffu, rs1, 2);
        if ((lane & 3) == 0) {
            degp[((size_t)(z*N_ + i0 + r0)) * 16 + jt*4 + wc]     = rs0;
            degp[((size_t)(z*N_ + i0 + r0 + 8)) * 16 + jt*4 + wc] = rs1;
        }
    }
    if (layer == 0) {
        __syncthreads();
        // coalesced copy sT -> g_gT16[z][j0+jl][i0+il]; 128 rows * 16 uint4
        const int tid = threadIdx.x;
        #pragma unroll
        for (int it = 0; it < 8; it++) {
            int idx = it * 256 + tid;        // 0..2047
            int jl = idx >> 4, c8 = (idx & 15) * 8;
            uint4 v = *(uint4*)(sT + jl * 136 + c8);
            *(uint4*)(g_gT16 + (size_t)z * N_ * N_ + (size_t)(j0 + jl) * N_ + i0 + c8) = v;
        }
    }
}

// dis = deg > 0 ? deg^-1/2 : 0
__global__ void k_dis(int layer) {
    const int i = blockIdx.x * blockDim.x + threadIdx.x;
    if (i >= RB_ * N_) return;
    const float* degp = layer ? g_degp2 : g_degp;
    float* dis        = layer ? g_dis2  : g_disv;
    float d = 0.f;
    #pragma unroll
    for (int p = 0; p < 16; p++) d += degp[(size_t)i * 16 + p];
    dis[i] = (d > 0.f) ? rsqrtf(d) : 0.f;
}

// gp[j][i] = dis[j]*gateT[j][i]*dis[i], fp16
__global__ void __launch_bounds__(256) k_gscale() {
    const int j = blockIdx.x, z = blockIdx.y;
    const float dj = g_disv[z*N_ + j];
    const size_t o = (size_t)z * N_ * N_ + (size_t)j * N_;
    const h16* row = g_gT16 + o;
    #pragma unroll
    for (int q = 0; q < 2; q++) {
        const int i = q * 256 + threadIdx.x;
        g_gp16[o + i] = __float2half(dj * __half2float(row[i]) * g_disv[z*N_ + i]);
    }
}

// feat1[j][d] = sum_i gp[j][i] * featT[b][d][i]
__global__ void __launch_bounds__(256, 2)
k_prop_tc() {
    extern __shared__ char smb[];
    const int z = blockIdx.z, b = z & (B_ - 1);
    const int j0 = blockIdx.x * 128, d0 = blockIdx.y * 128;
    const size_t ao = (size_t)z * N_ * N_ + (size_t)j0 * N_;
    const size_t bo = (size_t)b * D_ * N_ + (size_t)d0 * N_;
    float acc[16][4] = {};
    mma_main(g_gp16 + ao, N_, g_fT16 + bo, N_, 8, smb, acc);
    store_h(acc, g_f116 + ((size_t)z * N_ + j0) * D_ + d0, D_);
}

// feat2 at node 511 only
__global__ void __launch_bounds__(768) k_node2() {
    const int z = blockIdx.x;
    __shared__ float w[N_];
    const int tid = threadIdx.x;
    if (tid < N_) w[tid] = g_dis2[z*N_ + tid] * g_gcol2[z*N_ + tid];
    __syncthreads();
    const float disj = g_dis2[z*N_ + (N_-1)];
    const h16* F = g_f116 + (size_t)z * N_ * D_;
    float acc = 0.f;
    #pragma unroll 4
    for (int i = 0; i < N_; i++)
        acc = fmaf(w[i], __half2float(F[(size_t)i * D_ + tid]), acc);
    g_node2[(size_t)z * D_ + tid] = disj * acc;
}

// Per (r,b): retain gating at node 511, then 3-layer MLP head.
__global__ void __launch_bounds__(256) k_head(const float* __restrict__ feature,
                                              const float* __restrict__ proj_w,
                                              const float* __restrict__ proj_b,
                                              const float* __restrict__ fc1_w,
                                              const float* __restrict__ fc1_b,
                                              const float* __restrict__ fc2_w,
                                              const float* __restrict__ fc2_b,
                                              const float* __restrict__ fcf_w,
                                              const float* __restrict__ fcf_b,
                                              float* __restrict__ out) {
    const int z = blockIdx.x;
    const int r = z / B_, b = z % B_;
    const int tid = threadIdx.x;
    __shared__ float f0[D_], f1[D_], f2[D_], xs[D_];
    __shared__ float h1[FH_], h2[FH_];
    __shared__ float red[32];

    const float* pw = proj_w + r * D_;
    float s0 = 0.f, s1 = 0.f, s2 = 0.f;
    for (int d = tid; d < D_; d += 256) {
        float a  = feature[((size_t)b * N_ + (N_-1)) * D_ + d];
        float c1 = __half2float(g_f116[((size_t)z * N_ + (N_-1)) * D_ + d]);
        float c2 = g_node2[(size_t)z * D_ + d];
        float w  = pw[d];
        f0[d] = a; f1[d] = c1; f2[d] = c2;
        s0 = fmaf(a, w, s0); s1 = fmaf(c1, w, s1); s2 = fmaf(c2, w, s2);
    }
    #pragma unroll
    for (int m = 16; m > 0; m >>= 1) {
        s0 += __shfl_xor_sync(0xffffffffu, s0, m);
        s1 += __shfl_xor_sync(0xffffffffu, s1, m);
        s2 += __shfl_xor_sync(0xffffffffu, s2, m);
    }
    if ((tid & 31) == 0) { red[(tid>>5)*3+0] = s0; red[(tid>>5)*3+1] = s1; red[(tid>>5)*3+2] = s2; }
    __syncthreads();
    if (tid == 0) {
        float t0 = 0.f, t1 = 0.f, t2 = 0.f;
        for (int w = 0; w < 8; w++) { t0 += red[w*3+0]; t1 += red[w*3+1]; t2 += red[w*3+2]; }
        red[24] = t0; red[25] = t1; red[26] = t2;
    }
    __syncthreads();
    const float pb = proj_b[r];
    const float rt0 = 1.f / (1.f + expf(-(red[24] + pb)));
    const float rt1 = 1.f / (1.f + expf(-(red[25] + pb)));
    const float rt2 = 1.f / (1.f + expf(-(red[26] + pb)));
    __syncthreads();
    for (int d = tid; d < D_; d += 256)
        xs[d] = rt0 * f0[d] + rt1 * f1[d] + rt2 * f2[d];
    __syncthreads();

    {
        const float* Wr = fc1_w + (size_t)(r * FH_ + tid) * D_;
        float acc = fc1_b[r * FH_ + tid];
        #pragma unroll 4
        for (int d = 0; d < D_; d++) acc = fmaf(xs[d], Wr[d], acc);
        h1[tid] = fmaxf(acc, 0.f);
    }
    __syncthreads();
    {
        const float* Wr = fc2_w + (size_t)(r * FH_ + tid) * FH_;
        float acc = fc2_b[r * FH_ + tid];
        #pragma unroll 4
        for (int h = 0; h < FH_; h++) acc = fmaf(h1[h], Wr[h], acc);
        h2[tid] = fmaxf(acc, 0.f);
    }
    __syncthreads();
    if (tid < NC_) {
        const float* Wr = fcf_w + (size_t)(r * NC_ + tid) * FH_;
        float acc = fcf_b[r * NC_ + tid];
        for (int g = 0; g < FH_; g++) acc = fmaf(h2[g], Wr[g], acc);
        out[((size_t)b * NBR_ + r) * NC_ + tid] = acc;
    }
}

extern "C" void kernel_launch(void* const* d_in, const int* in_sizes, int n_in,
                              void* d_out, int out_size) {
    const float* pmask   = (const float*)d_in[0];
    const float* feature = (const float*)d_in[1];
    const float* Wq      = (const float*)d_in[2];
    const float* Wk      = (const float*)d_in[3];
    const float* proj_w  = (const float*)d_in[4];
    const float* proj_b  = (const float*)d_in[5];
    const float* fc1_w   = (const float*)d_in[6];
    const float* fc1_b   = (const float*)d_in[7];
    const float* fc2_w   = (const float*)d_in[8];
    const float* fc2_b   = (const float*)d_in[9];
    const float* fcf_w   = (const float*)d_in[10];
    const float* fcf_b   = (const float*)d_in[11];
    float* out = (float*)d_out;

    cudaFuncSetAttribute(k_mw_tc,   cudaFuncAttributeMaxDynamicSharedMemorySize, SMEM_REQ);
    cudaFuncSetAttribute(k_tf_tc,   cudaFuncAttributeMaxDynamicSharedMemorySize, SMEM_REQ);
    cudaFuncSetAttribute(k_gate_tc, cudaFuncAttributeMaxDynamicSharedMemorySize, SMEM_REQ);
    cudaFuncSetAttribute(k_prop_tc, cudaFuncAttributeMaxDynamicSharedMemorySize, SMEM_REQ);

    h16 *wq16, *wk16, *fe16;
    cudaGetSymbolAddress((void**)&wq16, g_Wq16);
    cudaGetSymbolAddress((void**)&wk16, g_Wk16);
    cudaGetSymbolAddress((void**)&fe16, g_fe16);

    // input conversions + feature transpose
    k_h <<<(NBR_*L_*D_*D_/4 + 255)/256, 256>>>(Wq, wq16, NBR_*L_*D_*D_/4);
    k_h <<<(NBR_*L_*D_*D_/4 + 255)/256, 256>>>(Wk, wk16, NBR_*L_*D_*D_/4);
    k_h <<<(B_*N_*D_/4 + 255)/256, 256>>>(feature, fe16, B_*N_*D_/4);
    k_tr<<<dim3(16, 24, B_), 256>>>(feature);
    k_mw_tc<<<dim3(6, 6, NBR_*L_), 256, SMEM_REQ>>>();

    // ---- layer 0 ----
    k_tf_tc  <<<dim3(128, 6, NBR_), 256, SMEM_REQ>>>(0);
    k_gate_tc<<<dim3(4, 4, RB_),    256, SMEM_REQ>>>(pmask, 0);
    k_dis    <<<(RB_*N_)/256, 256>>>(0);
    k_gscale <<<dim3(N_, RB_), 256>>>();
    k_prop_tc<<<dim3(4, 6, RB_),    256, SMEM_REQ>>>();

    // ---- layer 1 ----
    k_tf_tc  <<<dim3(128, 6, NBR_), 256, SMEM_REQ>>>(1);
    k_gate_tc<<<dim3(4, 4, RB_),    256, SMEM_REQ>>>(pmask, 1);
    k_dis    <<<(RB_*N_)/256, 256>>>(1);
    k_node2  <<<RB_, 768>>>();

    // ---- head ----
    k_head<<<RB_, 256>>>(feature, proj_w, proj_b, fc1_w, fc1_b,
                         fc2_w, fc2_b, fcf_w, fcf_b, out);
}

// round 13
// speedup vs baseline: 1.0506x; 1.0506x over previous
#include <cuda_runtime.h>
#include <cuda_fp16.h>
#include <math.h>
#include <stdint.h>

#define B_   32
#define N_   512
#define D_   768
#define NBR_ 4
#define L_   2
#define FH_  256
#define NC_  2
#define RB_  (NBR_*B_)   // 128

#define ISD 0.0360843918243516f  // 1/sqrt(768)

typedef __half h16;

// ---------------- scratch (device globals; allocation-free) ----------------
__device__ __align__(256) h16 g_Wq16[NBR_*L_*D_*D_];
__device__ __align__(256) h16 g_Wk16[NBR_*L_*D_*D_];
__device__ __align__(256) h16 g_Mt16[NBR_*L_*D_*D_];   // (Wq@Wk^T)^T = Wk@Wq^T [n][k]
__device__ __align__(256) h16 g_fe16[B_*N_*D_];        // feature fp16
__device__ __align__(256) h16 g_fT16[B_*D_*N_];        // feature^T fp16
__device__ __align__(256) h16 g_t16[NBR_*B_*N_*D_];    // feat@Mw
__device__ __align__(256) h16 g_gT16[RB_*N_*N_];       // layer-1 gate^T fp16 [z][j][i]
__device__ __align__(256) h16 g_gp16[RB_*N_*N_];       // dis*gateT*dis
__device__ __align__(256) h16 g_f116[RB_*N_*D_];       // feat1
__device__ float g_degp [RB_*N_*16];       // layer-1 degree partials
__device__ float g_disv [RB_*N_];          // layer-1 D^-1/2
__device__ float g_degp2[RB_*N_*16];       // layer-2 degree partials
__device__ float g_dis2 [RB_*N_];          // layer-2 D^-1/2
__device__ float g_gcol2[RB_*N_];          // layer-2 gate column j=511
__device__ float g_node2[RB_*D_];          // layer-2 node-511 features

// ===================== warp-MMA (fp16 HMMA) machinery =======================
// 128x128 C-tile, K-chunk 64, 256 threads = 8 warps in 2(m) x 4(n).
// Single-pass fp16. 2-stage cp.async (R11-proven), 2 CTAs/SM.

#define KPAD     72                       // fp16 per smem row (144 B)
#define TILE_B   (128*KPAD*2)             // 18432 B per operand tile
#define OFF_A    0
#define OFF_B    (TILE_B)
#define STAGE_B  (2*TILE_B)               // 36864
#define SMEM_REQ (2*STAGE_B)              // 73728 -> 2 CTAs/SM

__device__ __forceinline__ uint32_t smem_u32(const void* p) {
    uint32_t a;
    asm("{ .reg .u64 t; cvta.to.shared.u64 t, %1; cvt.u32.u64 %0, t; }"
        : "=r"(a) : "l"(p));
    return a;
}

__device__ __forceinline__ void ldsm4(uint32_t r[4], uint32_t addr) {
    asm volatile("ldmatrix.sync.aligned.m8n8.x4.shared.b16 {%0,%1,%2,%3}, [%4];"
                 : "=r"(r[0]), "=r"(r[1]), "=r"(r[2]), "=r"(r[3]) : "r"(addr));
}

__device__ __forceinline__ void mma_fp16(float c[4], const uint32_t a[4],
                                         uint32_t b0, uint32_t b1) {
    asm volatile(
        "mma.sync.aligned.m16n8k16.row.col.f32.f16.f16.f32 "
        "{%0,%1,%2,%3}, {%4,%5,%6,%7}, {%8,%9}, {%0,%1,%2,%3};"
        : "+f"(c[0]), "+f"(c[1]), "+f"(c[2]), "+f"(c[3])
        : "r"(a[0]), "r"(a[1]), "r"(a[2]), "r"(a[3]), "r"(b0), "r"(b1));
}

__device__ __forceinline__ void cpa16(uint32_t dst, const void* src) {
    asm volatile("cp.async.cg.shared.global [%0], [%1], 16;"
                 :: "r"(dst), "l"(src) : "memory");
}

// issue cp.async for one 64-K chunk: 2 tiles of 128x64 fp16 (128 B/row)
__device__ __forceinline__ void cpa_chunk(uint32_t sdst,
                                          const h16* __restrict__ A, int lda,
                                          const h16* __restrict__ Bm, int ldb,
                                          int k0) {
    const int tid = threadIdx.x;
    #pragma unroll
    for (int it = 0; it < 8; it++) {
        const int idx  = it * 256 + tid;   // 2048 = 2 tiles * 128 rows * 8 groups
        const int tile = idx >> 10;
        const int row  = (idx >> 3) & 127;
        const int grp  = idx & 7;
        const h16* src = tile ? Bm : A;
        const int ld   = tile ? ldb : lda;
        cpa16(sdst + (tile ? OFF_B : OFF_A) + row * 144 + grp * 16,
              src + (size_t)row * ld + k0 + grp * 8);
    }
}

// one 64-K chunk of MMAs; acc[16][4] per thread
__device__ __forceinline__ void mma_chunk(uint32_t sbase, float (*acc)[4]) {
    const int lane = threadIdx.x & 31;
    const int wid  = threadIdx.x >> 5;
    const int wr = wid >> 2, wc = wid & 3;
    uint32_t aoff[4], boff[2];
    #pragma unroll
    for (int mt = 0; mt < 4; mt++)
        aoff[mt] = (uint32_t)(((wr*64 + mt*16 + (lane & 7) + ((lane >> 3) & 1) * 8) * KPAD
                               + (lane >> 4) * 8) * 2);
    #pragma unroll
    for (int pr = 0; pr < 2; pr++)
        boff[pr] = (uint32_t)(((wc*32 + pr*16 + ((lane >> 4) & 1) * 8 + (lane & 7)) * KPAD
                               + ((lane >> 3) & 1) * 8) * 2);
    #pragma unroll
    for (int ks = 0; ks < 4; ks++) {
        const uint32_t kb = ks * 32;       // 16 fp16 = 32 B
        uint32_t A[4][4], Bv[4][2];
        // B first: every mma needs B; A[0] arrives right after
        #pragma unroll
        for (int pr = 0; pr < 2; pr++) {
            uint32_t rr[4];
            ldsm4(rr, sbase + OFF_B + boff[pr] + kb);
            Bv[pr*2][0] = rr[0]; Bv[pr*2][1] = rr[1];
            Bv[pr*2+1][0] = rr[2]; Bv[pr*2+1][1] = rr[3];
        }
        #pragma unroll
        for (int mt = 0; mt < 4; mt++) ldsm4(A[mt], sbase + OFF_A + aoff[mt] + kb);
        #pragma unroll
        for (int mt = 0; mt < 4; mt++)
            #pragma unroll
            for (int nt = 0; nt < 4; nt++)
                mma_fp16(acc[mt*4+nt], A[mt], Bv[nt][0], Bv[nt][1]);
    }
}

// full mainloop: 2-stage double-buffered cp.async (R11-proven)
__device__ __forceinline__ void mma_main(const h16* __restrict__ A, int lda,
                                         const h16* __restrict__ Bm, int ldb,
                                         int kchunks, char* smb, float (*acc)[4]) {
    uint32_t sb = smem_u32(smb);
    cpa_chunk(sb, A, lda, Bm, ldb, 0);
    asm volatile("cp.async.commit_group;" ::: "memory");
    for (int c = 0; c < kchunks; c++) {
        if (c + 1 < kchunks) {
            cpa_chunk(sb + ((c+1)&1)*STAGE_B, A, lda, Bm, ldb, (c+1)*64);
            asm volatile("cp.async.commit_group;" ::: "memory");
            asm volatile("cp.async.wait_group 1;" ::: "memory");
        } else {
            asm volatile("cp.async.wait_group 0;" ::: "memory");
        }
        __syncthreads();
        mma_chunk(sb + (c&1)*STAGE_B, acc);
        __syncthreads();
    }
}

// store acc as fp16
__device__ __forceinline__ void store_h(float (*acc)[4], h16* __restrict__ C, int ldc) {
    const int lane = threadIdx.x & 31;
    const int wid  = threadIdx.x >> 5;
    const int wr = wid >> 2, wc = wid & 3;
    #pragma unroll
    for (int mt = 0; mt < 4; mt++) {
        const int r0 = wr*64 + mt*16 + (lane >> 2);
        #pragma unroll
        for (int nt = 0; nt < 4; nt++) {
            const int cn = wc*32 + nt*8 + (lane & 3) * 2;
            float* f = acc[mt*4+nt];
            *(__half2*)(C + (size_t)r0 * ldc + cn)     = __floats2half2_rn(f[0], f[1]);
            *(__half2*)(C + (size_t)(r0+8) * ldc + cn) = __floats2half2_rn(f[2], f[3]);
        }
    }
}

// ============================ kernels =======================================

// elementwise fp32 -> fp16
__global__ void __launch_bounds__(256) k_h(const float* __restrict__ src,
                                           h16* __restrict__ dst, int n4) {
    const int i = blockIdx.x * 256 + threadIdx.x;
    if (i >= n4) return;
    float4 v = ((const float4*)src)[i];
    ((__half2*)dst)[i*2]   = __floats2half2_rn(v.x, v.y);
    ((__half2*)dst)[i*2+1] = __floats2half2_rn(v.z, v.w);
}

// featT[b][d][i] = feature[b][i][d], fp16
__global__ void __launch_bounds__(256) k_tr(const float* __restrict__ f) {
    __shared__ float t[32][33];
    const int b = blockIdx.z;
    const int i0 = blockIdx.x * 32, d0 = blockIdx.y * 32;
    const int tx = threadIdx.x & 31, ty = threadIdx.x >> 5;
    #pragma unroll
    for (int s = 0; s < 32; s += 8)
        t[ty + s][tx] = f[((size_t)b * N_ + i0 + ty + s) * D_ + d0 + tx];
    __syncthreads();
    #pragma unroll
    for (int s = 0; s < 32; s += 8)
        g_fT16[((size_t)b * D_ + d0 + ty + s) * N_ + i0 + tx] = __float2half(t[tx][ty + s]);
}

// Mt[z] = Wk[z] @ Wq[z]^T
__global__ void __launch_bounds__(256, 2)
k_mw_tc() {
    extern __shared__ char smb[];
    const int z = blockIdx.z, m0 = blockIdx.x * 128, n0 = blockIdx.y * 128;
    const size_t zo = (size_t)z * D_ * D_;
    float acc[16][4] = {};
    mma_main(g_Wk16 + zo + (size_t)m0 * D_, D_,
             g_Wq16 + zo + (size_t)n0 * D_, D_, 12, smb, acc);
    store_h(acc, g_Mt16 + zo + (size_t)m0 * D_ + n0, D_);
}

// t = featIn @ Mw[r,layer]
__global__ void __launch_bounds__(256, 2)
k_tf_tc(int layer) {
    extern __shared__ char smb[];
    const int r = blockIdx.z, m0 = blockIdx.x * 128, n0 = blockIdx.y * 128;
    const size_t ao = (size_t)r * B_ * N_ * D_ + (size_t)m0 * D_;
    const h16* Ap = layer ? (g_f116 + ao) : (g_fe16 + (size_t)m0 * D_);
    const size_t bo = (size_t)(r * L_ + layer) * D_ * D_ + (size_t)n0 * D_;
    float acc[16][4] = {};
    mma_main(Ap, D_, g_Mt16 + bo, D_, 12, smb, acc);
    store_h(acc, g_t16 + ((size_t)r * B_ * N_ + m0) * D_ + n0, D_);
}

// logits = t @ featB^T; gate epilogue + deterministic row-sum partials.
__global__ void __launch_bounds__(256, 2)
k_gate_tc(const float* __restrict__ pmask, int layer) {
    extern __shared__ char smb[];
    const int z = blockIdx.z, b = z & (B_ - 1);
    const int i0 = blockIdx.x * 128, j0 = blockIdx.y * 128, jt = blockIdx.y;
    const size_t ao = (size_t)z * N_ * D_ + (size_t)i0 * D_;
    const size_t bo = layer ? ((size_t)z * N_ * D_ + (size_t)j0 * D_)
                            : ((size_t)b * N_ * D_ + (size_t)j0 * D_);
    const h16* Bp = layer ? (g_f116 + bo) : (g_fe16 + bo);
    float acc[16][4] = {};
    mma_main(g_t16 + ao, D_, Bp, D_, 12, smb, acc);

    const int lane = threadIdx.x & 31;
    const int wid  = threadIdx.x >> 5;
    const int wr = wid >> 2, wc = wid & 3;
    h16* sT = (h16*)smb;                   // [128][136] j-major fp16 transpose buffer

    float* degp = layer ? g_degp2 : g_degp;
    #pragma unroll
    for (int mt = 0; mt < 4; mt++) {
        const int r0 = wr*64 + mt*16 + (lane >> 2);
        const float pmi0 = pmask[b*N_ + i0 + r0];
        const float pmi1 = pmask[b*N_ + i0 + r0 + 8];
        float rs0 = 0.f, rs1 = 0.f;
        #pragma unroll
        for (int nt = 0; nt < 4; nt++) {
            const int cn = wc*32 + nt*8 + (lane & 3) * 2;
            const float pj0 = pmask[b*N_ + j0 + cn];
            const float pj1 = pmask[b*N_ + j0 + cn + 1];
            float* f = acc[mt*4+nt];
            #pragma unroll
            for (int e = 0; e < 4; e++) {
                const float pmi = (e < 2) ? pmi0 : pmi1;
                const float pmj = (e & 1) ? pj1 : pj0;
                const float s = f[e] * ISD;
                const float p = 1.f / (1.f + __expf(-s));
                const float g = fminf(fmaxf(fmaf(p, 1.2f, -0.1f), 0.f), 1.f) * pmi * pmj;
                const int jl = cn + (e & 1);
                const int il = (e < 2) ? r0 : (r0 + 8);
                if (layer == 0) {
                    sT[jl * 136 + il] = __float2half(g);
                } else if (j0 + jl == N_ - 1) {
                    g_gcol2[z*N_ + i0 + il] = g;
                }
                if (e < 2) rs0 += g; else rs1 += g;
            }
        }
        rs0 += __shfl_xor_sync(0xffffffffu, rs0, 1);
        rs0 += __shfl_xor_sync(0xffffffffu, rs0, 2);
        rs1 += __shfl_xor_sync(0xffffffffu, rs1, 1);
        rs1 += __shfl_xor_sync(0xffffffffu, rs1, 2);
        if ((lane & 3) == 0) {
            degp[((size_t)(z*N_ + i0 + r0)) * 16 + jt*4 + wc]     = rs0;
            degp[((size_t)(z*N_ + i0 + r0 + 8)) * 16 + jt*4 + wc] = rs1;
        }
    }
    if (layer == 0) {
        __syncthreads();
        // coalesced copy sT -> g_gT16[z][j0+jl][i0+il]; 128 rows * 16 uint4
        const int tid = threadIdx.x;
        #pragma unroll
        for (int it = 0; it < 8; it++) {
            int idx = it * 256 + tid;        // 0..2047
            int jl = idx >> 4, c8 = (idx & 15) * 8;
            uint4 v = *(uint4*)(sT + jl * 136 + c8);
            *(uint4*)(g_gT16 + (size_t)z * N_ * N_ + (size_t)(j0 + jl) * N_ + i0 + c8) = v;
        }
    }
}

// dis = deg > 0 ? deg^-1/2 : 0
__global__ void k_dis(int layer) {
    const int i = blockIdx.x * blockDim.x + threadIdx.x;
    if (i >= RB_ * N_) return;
    const float* degp = layer ? g_degp2 : g_degp;
    float* dis        = layer ? g_dis2  : g_disv;
    float d = 0.f;
    #pragma unroll
    for (int p = 0; p < 16; p++) d += degp[(size_t)i * 16 + p];
    dis[i] = (d > 0.f) ? rsqrtf(d) : 0.f;
}

// gp[j][i] = dis[j]*gT[j][i]*dis[i], fp16, vectorized uint4 (8-wide)
__global__ void __launch_bounds__(256) k_gscale() {
    const int z = blockIdx.y, j0 = blockIdx.x * 8;
    __shared__ float sdi[N_];
    const int tid = threadIdx.x;
    for (int i = tid; i < N_; i += 256) sdi[i] = g_disv[z*N_ + i];
    __syncthreads();
    #pragma unroll
    for (int q = 0; q < 2; q++) {
        const int idx = q * 256 + tid;       // 0..511
        const int jr  = idx >> 6;            // 8 rows
        const int seg = idx & 63;            // 64 uint4 per row
        const int j   = j0 + jr;
        const float dj = sdi[j];
        const size_t o = (size_t)z * N_ * N_ + (size_t)j * N_ + seg * 8;
        uint4 v = *(const uint4*)(g_gT16 + o);
        const h16* hv = (const h16*)&v;
        uint4 w;
        h16* hw = (h16*)&w;
        #pragma unroll
        for (int k = 0; k < 8; k++)
            hw[k] = __float2half(dj * __half2float(hv[k]) * sdi[seg * 8 + k]);
        *(uint4*)(g_gp16 + o) = w;
    }
}

// feat1[j][d] = sum_i gp[j][i] * featT[b][d][i]
__global__ void __launch_bounds__(256, 2)
k_prop_tc() {
    extern __shared__ char smb[];
    const int z = blockIdx.z, b = z & (B_ - 1);
    const int j0 = blockIdx.x * 128, d0 = blockIdx.y * 128;
    const size_t ao = (size_t)z * N_ * N_ + (size_t)j0 * N_;
    const size_t bo = (size_t)b * D_ * N_ + (size_t)d0 * N_;
    float acc[16][4] = {};
    mma_main(g_gp16 + ao, N_, g_fT16 + bo, N_, 8, smb, acc);
    store_h(acc, g_f116 + ((size_t)z * N_ + j0) * D_ + d0, D_);
}

// feat2 at node 511 only
__global__ void __launch_bounds__(768) k_node2() {
    const int z = blockIdx.x;
    __shared__ float w[N_];
    const int tid = threadIdx.x;
    if (tid < N_) w[tid] = g_dis2[z*N_ + tid] * g_gcol2[z*N_ + tid];
    __syncthreads();
    const float disj = g_dis2[z*N_ + (N_-1)];
    const h16* F = g_f116 + (size_t)z * N_ * D_;
    float acc = 0.f;
    #pragma unroll 4
    for (int i = 0; i < N_; i++)
        acc = fmaf(w[i], __half2float(F[(size_t)i * D_ + tid]), acc);
    g_node2[(size_t)z * D_ + tid] = disj * acc;
}

// Per (r,b): retain gating at node 511, then 3-layer MLP head.
__global__ void __launch_bounds__(256) k_head(const float* __restrict__ feature,
                                              const float* __restrict__ proj_w,
                                              const float* __restrict__ proj_b,
                                              const float* __restrict__ fc1_w,
                                              const float* __restrict__ fc1_b,
                                              const float* __restrict__ fc2_w,
                                              const float* __restrict__ fc2_b,
                                              const float* __restrict__ fcf_w,
                                              const float* __restrict__ fcf_b,
                                              float* __restrict__ out) {
    const int z = blockIdx.x;
    const int r = z / B_, b = z % B_;
    const int tid = threadIdx.x;
    __shared__ float f0[D_], f1[D_], f2[D_], xs[D_];
    __shared__ float h1[FH_], h2[FH_];
    __shared__ float red[32];

    const float* pw = proj_w + r * D_;
    float s0 = 0.f, s1 = 0.f, s2 = 0.f;
    for (int d = tid; d < D_; d += 256) {
        float a  = feature[((size_t)b * N_ + (N_-1)) * D_ + d];
        float c1 = __half2float(g_f116[((size_t)z * N_ + (N_-1)) * D_ + d]);
        float c2 = g_node2[(size_t)z * D_ + d];
        float w  = pw[d];
        f0[d] = a; f1[d] = c1; f2[d] = c2;
        s0 = fmaf(a, w, s0); s1 = fmaf(c1, w, s1); s2 = fmaf(c2, w, s2);
    }
    #pragma unroll
    for (int m = 16; m > 0; m >>= 1) {
        s0 += __shfl_xor_sync(0xffffffffu, s0, m);
        s1 += __shfl_xor_sync(0xffffffffu, s1, m);
        s2 += __shfl_xor_sync(0xffffffffu, s2, m);
    }
    if ((tid & 31) == 0) { red[(tid>>5)*3+0] = s0; red[(tid>>5)*3+1] = s1; red[(tid>>5)*3+2] = s2; }
    __syncthreads();
    if (tid == 0) {
        float t0 = 0.f, t1 = 0.f, t2 = 0.f;
        for (int w = 0; w < 8; w++) { t0 += red[w*3+0]; t1 += red[w*3+1]; t2 += red[w*3+2]; }
        red[24] = t0; red[25] = t1; red[26] = t2;
    }
    __syncthreads();
    const float pb = proj_b[r];
    const float rt0 = 1.f / (1.f + expf(-(red[24] + pb)));
    const float rt1 = 1.f / (1.f + expf(-(red[25] + pb)));
    const float rt2 = 1.f / (1.f + expf(-(red[26] + pb)));
    __syncthreads();
    for (int d = tid; d < D_; d += 256)
        xs[d] = rt0 * f0[d] + rt1 * f1[d] + rt2 * f2[d];
    __syncthreads();

    {
        const float* Wr = fc1_w + (size_t)(r * FH_ + tid) * D_;
        float acc = fc1_b[r * FH_ + tid];
        #pragma unroll 4
        for (int d = 0; d < D_; d++) acc = fmaf(xs[d], Wr[d], acc);
        h1[tid] = fmaxf(acc, 0.f);
    }
    __syncthreads();
    {
        const float* Wr = fc2_w + (size_t)(r * FH_ + tid) * FH_;
        float acc = fc2_b[r * FH_ + tid];
        #pragma unroll 4
        for (int h = 0; h < FH_; h++) acc = fmaf(h1[h], Wr[h], acc);
        h2[tid] = fmaxf(acc, 0.f);
    }
    __syncthreads();
    if (tid < NC_) {
        const float* Wr = fcf_w + (size_t)(r * NC_ + tid) * FH_;
        float acc = fcf_b[r * NC_ + tid];
        for (int g = 0; g < FH_; g++) acc = fmaf(h2[g], Wr[g], acc);
        out[((size_t)b * NBR_ + r) * NC_ + tid] = acc;
    }
}

extern "C" void kernel_launch(void* const* d_in, const int* in_sizes, int n_in,
                              void* d_out, int out_size) {
    const float* pmask   = (const float*)d_in[0];
    const float* feature = (const float*)d_in[1];
    const float* Wq      = (const float*)d_in[2];
    const float* Wk      = (const float*)d_in[3];
    const float* proj_w  = (const float*)d_in[4];
    const float* proj_b  = (const float*)d_in[5];
    const float* fc1_w   = (const float*)d_in[6];
    const float* fc1_b   = (const float*)d_in[7];
    const float* fc2_w   = (const float*)d_in[8];
    const float* fc2_b   = (const float*)d_in[9];
    const float* fcf_w   = (const float*)d_in[10];
    const float* fcf_b   = (const float*)d_in[11];
    float* out = (float*)d_out;

    cudaFuncSetAttribute(k_mw_tc,   cudaFuncAttributeMaxDynamicSharedMemorySize, SMEM_REQ);
    cudaFuncSetAttribute(k_tf_tc,   cudaFuncAttributeMaxDynamicSharedMemorySize, SMEM_REQ);
    cudaFuncSetAttribute(k_gate_tc, cudaFuncAttributeMaxDynamicSharedMemorySize, SMEM_REQ);
    cudaFuncSetAttribute(k_prop_tc, cudaFuncAttributeMaxDynamicSharedMemorySize, SMEM_REQ);

    h16 *wq16, *wk16, *fe16;
    cudaGetSymbolAddress((void**)&wq16, g_Wq16);
    cudaGetSymbolAddress((void**)&wk16, g_Wk16);
    cudaGetSymbolAddress((void**)&fe16, g_fe16);

    // input conversions (launches 1-3)
    k_h <<<(NBR_*L_*D_*D_/4 + 255)/256, 256>>>(Wq, wq16, NBR_*L_*D_*D_/4);
    k_h <<<(NBR_*L_*D_*D_/4 + 255)/256, 256>>>(Wk, wk16, NBR_*L_*D_*D_/4);
    k_h <<<(B_*N_*D_/4 + 255)/256, 256>>>(feature, fe16, B_*N_*D_/4);
    k_mw_tc<<<dim3(6, 6, NBR_*L_), 256, SMEM_REQ>>>();                    // launch 4

    // ---- layer 0 ----
    k_tf_tc  <<<dim3(128, 6, NBR_), 256, SMEM_REQ>>>(0);                  // launch 5
    k_gate_tc<<<dim3(4, 4, RB_),    256, SMEM_REQ>>>(pmask, 0);           // launch 6 <- ncu
    k_tr     <<<dim3(16, 24, B_), 256>>>(feature);   // needed only by k_prop
    k_dis    <<<(RB_*N_)/256, 256>>>(0);
    k_gscale <<<dim3(N_/8, RB_), 256>>>();
    k_prop_tc<<<dim3(4, 6, RB_),    256, SMEM_REQ>>>();

    // ---- layer 1 ----
    k_tf_tc  <<<dim3(128, 6, NBR_), 256, SMEM_REQ>>>(1);
    k_gate_tc<<<dim3(4, 4, RB_),    256, SMEM_REQ>>>(pmask, 1);
    k_dis    <<<(RB_*N_)/256, 256>>>(1);
    k_node2  <<<RB_, 768>>>();

    // ---- head ----
    k_head<<<RB_, 256>>>(feature, proj_w, proj_b, fc1_w, fc1_b,
                         fc2_w, fc2_b, fcf_w, fcf_b, out);
}